// round 8
// baseline (speedup 1.0000x reference)
#include <cuda_runtime.h>
#include <cuda_fp16.h>
#include <math.h>

#define NN 100000
#define EE 1000000
#define NRMAX (NN * 4)
#define NIDX_CAP 100992

// ---------------- device scratch ----------------
__device__ __half g_h0h[(size_t)NN * 128];
__device__ __half g_h1h[(size_t)NN * 256];
__device__ __half g_h2h[(size_t)NN * 256];
__device__ float  g_h3[(size_t)NN * 128];
__device__ __half g_xh[(size_t)NN * 128];
__device__ __half g_wnth[7 * 128 * 128];   // transposed [t][n][k]
__device__ __half g_wbh[655360];           // packed transposed [n][Ktot] per layer
__device__ float g_pool[16 * 128];
__device__ float g_gcnt[16];

__device__ int g_cnt[NRMAX];
__device__ int g_off[NRMAX];
__device__ int g_cur[NRMAX];
__device__ int g_bsum[1024];
__device__ int g_eidx[EE];
__device__ int g_nt_cnt[8];
__device__ int g_nt_off[8];
__device__ int g_nt_cur[8];
__device__ int g_nidx[NIDX_CAP];

// ---------------- helpers ----------------
__device__ __forceinline__ void cp16h(__half* dst, const __half* src, bool pred) {
    unsigned d = (unsigned)__cvta_generic_to_shared(dst);
    int sz = pred ? 16 : 0;
    asm volatile("cp.async.ca.shared.global [%0], [%1], 16, %2;\n"
                 :: "r"(d), "l"(src), "r"(sz));
}
#define CP_COMMIT() asm volatile("cp.async.commit_group;\n")
#define CP_WAIT1()  asm volatile("cp.async.wait_group 1;\n")
#define CP_WAIT0()  asm volatile("cp.async.wait_group 0;\n")

__device__ __forceinline__ void mma_f16(float* c, const unsigned* a, unsigned b0, unsigned b1) {
    asm volatile(
        "mma.sync.aligned.m16n8k16.row.col.f32.f16.f16.f32 "
        "{%0,%1,%2,%3},{%4,%5,%6,%7},{%8,%9},{%0,%1,%2,%3};"
        : "+f"(c[0]), "+f"(c[1]), "+f"(c[2]), "+f"(c[3])
        : "r"(a[0]), "r"(a[1]), "r"(a[2]), "r"(a[3]), "r"(b0), "r"(b1));
}
__device__ __forceinline__ unsigned h2u(__half2 h) { return *(unsigned*)&h; }

// ---------------- init / conversion kernels ----------------
__global__ void k_init(int NR) {
    int i = blockIdx.x * blockDim.x + threadIdx.x;
    if (i < NR) g_cnt[i] = 0;
    if (i < NIDX_CAP) g_nidx[i] = -1;
    if (i < 8) g_nt_cnt[i] = 0;
    if (i < 2048) g_pool[i] = 0.f;
    if (i < 16) g_gcnt[i] = 0.f;
}
__global__ void k_zero_out(float* out, int n) {
    int i = blockIdx.x * blockDim.x + threadIdx.x;
    if (i < n) out[i] = 0.f;
}
__global__ void k_cvt_x(const float4* __restrict__ src, uint4* __restrict__ dst, int n8) {
    int i = blockIdx.x * blockDim.x + threadIdx.x;
    if (i < n8) {
        float4 a = src[i * 2], b = src[i * 2 + 1];
        uint4 o;
        o.x = h2u(__floats2half2_rn(a.x, a.y));
        o.y = h2u(__floats2half2_rn(a.z, a.w));
        o.z = h2u(__floats2half2_rn(b.x, b.y));
        o.w = h2u(__floats2half2_rn(b.z, b.w));
        dst[i] = o;
    }
}
__global__ void k_pack_wnt(const float* __restrict__ src) {
    int i = blockIdx.x * blockDim.x + threadIdx.x;
    if (i < 7 * 128 * 128) {
        int t = i >> 14, rem = i & 16383;
        int n = rem >> 7, k = rem & 127;
        g_wnth[i] = __float2half_rn(src[(t << 14) + (k << 7) + n]);
    }
}
__global__ void k_pack_wb(const float* __restrict__ Wr, const float* __restrict__ Ws,
                          __half* __restrict__ dst, int K1, int Ktot, int Nout, int total) {
    int j = blockIdx.x * blockDim.x + threadIdx.x;
    if (j < total) {
        int n = j / Ktot, kk = j - n * Ktot;
        float v = (kk < K1) ? Wr[(size_t)kk * Nout + n]
                            : Ws[(size_t)(kk - K1) * Nout + n];
        dst[j] = __float2half_rn(v);
    }
}

// ---------------- edge CSR build ----------------
__global__ void k_hist(const int* __restrict__ dst, const int* __restrict__ typ, int E) {
    int e = blockIdx.x * blockDim.x + threadIdx.x;
    if (e < E) atomicAdd(&g_cnt[dst[e] * 4 + typ[e]], 1);
}
__device__ __forceinline__ int block_scan_incl(int v, int* ws) {
    int lane = threadIdx.x & 31, wid = threadIdx.x >> 5;
#pragma unroll
    for (int o = 1; o < 32; o <<= 1) {
        int t = __shfl_up_sync(0xffffffffu, v, o);
        if (lane >= o) v += t;
    }
    if (lane == 31) ws[wid] = v;
    __syncthreads();
    if (wid == 0) {
        int w = (lane < (int)(blockDim.x >> 5)) ? ws[lane] : 0;
#pragma unroll
        for (int o = 1; o < 32; o <<= 1) {
            int t = __shfl_up_sync(0xffffffffu, w, o);
            if (lane >= o) w += t;
        }
        ws[lane] = w;
    }
    __syncthreads();
    return v + (wid > 0 ? ws[wid - 1] : 0);
}
__global__ void k_scan1(int n) {
    __shared__ int ws[32];
    int i = blockIdx.x * 1024 + threadIdx.x;
    int c = (i < n) ? g_cnt[i] : 0;
    int incl = block_scan_incl(c, ws);
    if (i < n) g_off[i] = incl - c;
    if (threadIdx.x == 1023) g_bsum[blockIdx.x] = incl;
}
__global__ void k_scan2(int nb) {
    __shared__ int ws[32];
    int i = threadIdx.x;
    int v = (i < nb) ? g_bsum[i] : 0;
    int incl = block_scan_incl(v, ws);
    if (i < nb) g_bsum[i] = incl - v;
}
__global__ void k_scan3(int n) {
    int i = blockIdx.x * 1024 + threadIdx.x;
    if (i < n) {
        int o = g_off[i] + g_bsum[i >> 10];
        g_off[i] = o;
        g_cur[i] = o;
    }
}
__global__ void k_bucket(const int* __restrict__ src, const int* __restrict__ dst,
                         const int* __restrict__ typ, int E) {
    int e = blockIdx.x * blockDim.x + threadIdx.x;
    if (e < E) {
        int key = dst[e] * 4 + typ[e];
        int pos = atomicAdd(&g_cur[key], 1);
        g_eidx[pos] = src[e];
    }
}

// ---------------- node-type counting sort ----------------
__global__ void k_hist_nt(const int* __restrict__ nt, int N) {
    int n = blockIdx.x * blockDim.x + threadIdx.x;
    unsigned act = __ballot_sync(0xffffffffu, n < N);
    if (n < N) {
        int t = nt[n];
        unsigned m = __match_any_sync(act, t);
        if ((threadIdx.x & 31) == __ffs(m) - 1) atomicAdd(&g_nt_cnt[t], __popc(m));
    }
}
__global__ void k_nt_offsets() {
    if (threadIdx.x == 0) {
        int off = 0;
        for (int t = 0; t < 7; t++) {
            g_nt_off[t] = off;
            g_nt_cur[t] = off;
            off += ((g_nt_cnt[t] + 127) / 128) * 128;
        }
        g_nt_off[7] = off;
    }
}
__global__ void k_bucket_nt(const int* __restrict__ nt, int N) {
    int n = blockIdx.x * blockDim.x + threadIdx.x;
    unsigned act = __ballot_sync(0xffffffffu, n < N);
    if (n < N) {
        int t = nt[n];
        unsigned m = __match_any_sync(act, t);
        int leader = __ffs(m) - 1;
        unsigned lt = (1u << (threadIdx.x & 31)) - 1u;
        int rank = __popc(m & lt);
        int base = 0;
        if ((threadIdx.x & 31) == leader) base = atomicAdd(&g_nt_cur[t], __popc(m));
        base = __shfl_sync(act, base, leader);
        g_nidx[base + rank] = n;
    }
}

// ---------------- encoder: fp16 tc GEMM with row indirection ----------------
__global__ void __launch_bounds__(256) k_enc_h() {
    extern __shared__ __half sm[];
    __half* As = sm;                 // 3*128*40
    __half* Bs = sm + 3 * 128 * 40;  // 3*128*40
#define HAS(b, m, k) As[((b) * 128 + (m)) * 40 + (k)]
#define HBS(b, n, k) Bs[((b) * 128 + (n)) * 40 + (k)]

    int base = blockIdx.x * 128;
    if (base >= g_nt_off[7]) return;
    int t = 0;
    while (t < 6 && base >= g_nt_off[t + 1]) t++;
    const __half* W = g_wnth + (size_t)t * 16384;

    int tid = threadIdx.x;
    int lane = tid & 31, warp = tid >> 5;
    int lr = lane >> 2, lc = lane & 3;
    int wm = (warp & 3) * 32;
    int wn = (warp >> 2) * 64;

    int ar = tid >> 1;
    int ao = (tid & 1) * 16;
    int anode = g_nidx[base + ar];
    const __half* asrc = g_xh + (size_t)max(anode, 0) * 128;
    bool avalid = anode >= 0;

    float acc[2][8][4];
#pragma unroll
    for (int i = 0; i < 2; i++)
#pragma unroll
        for (int j = 0; j < 8; j++)
#pragma unroll
            for (int q = 0; q < 4; q++) acc[i][j][q] = 0.f;

    auto stage = [&](int s, int buf) {
        int k0 = s * 32;
        cp16h(&HAS(buf, ar, ao), asrc + k0 + ao, avalid);
        cp16h(&HAS(buf, ar, ao + 8), asrc + k0 + ao + 8, avalid);
        const __half* bp = W + (size_t)ar * 128 + k0;
        cp16h(&HBS(buf, ar, ao), bp + ao, true);
        cp16h(&HBS(buf, ar, ao + 8), bp + ao + 8, true);
    };

    const int NSLAB = 4;
    stage(0, 0); CP_COMMIT();
    stage(1, 1); CP_COMMIT();
    for (int s = 0; s < NSLAB; s++) {
        if (s + 1 < NSLAB) CP_WAIT1(); else CP_WAIT0();
        __syncthreads();
        if (s + 2 < NSLAB) { stage(s + 2, (s + 2) % 3); CP_COMMIT(); }
        int buf = s % 3;
#pragma unroll
        for (int ks = 0; ks < 2; ks++) {
            int kb = ks * 16 + 2 * lc;
            unsigned af[2][4];
#pragma unroll
            for (int mt = 0; mt < 2; mt++) {
                int r = wm + mt * 16 + lr;
                af[mt][0] = *(unsigned*)&HAS(buf, r, kb);
                af[mt][1] = *(unsigned*)&HAS(buf, r + 8, kb);
                af[mt][2] = *(unsigned*)&HAS(buf, r, kb + 8);
                af[mt][3] = *(unsigned*)&HAS(buf, r + 8, kb + 8);
            }
#pragma unroll
            for (int nt = 0; nt < 8; nt++) {
                int n = wn + nt * 8 + lr;
                unsigned b0 = *(unsigned*)&HBS(buf, n, kb);
                unsigned b1 = *(unsigned*)&HBS(buf, n, kb + 8);
#pragma unroll
                for (int mt = 0; mt < 2; mt++) mma_f16(acc[mt][nt], af[mt], b0, b1);
            }
        }
        __syncthreads();
    }

#pragma unroll
    for (int mt = 0; mt < 2; mt++) {
        int r0 = base + wm + mt * 16 + lr;
        int n0 = g_nidx[r0], n1 = g_nidx[r0 + 8];
#pragma unroll
        for (int nt = 0; nt < 8; nt++) {
            int c = wn + nt * 8 + 2 * lc;
            if (n0 >= 0) *(__half2*)(g_h0h + (size_t)n0 * 128 + c) =
                __floats2half2_rn(acc[mt][nt][0], acc[mt][nt][1]);
            if (n1 >= 0) *(__half2*)(g_h0h + (size_t)n1 * 128 + c) =
                __floats2half2_rn(acc[mt][nt][2], acc[mt][nt][3]);
        }
    }
#undef HAS
#undef HBS
}

// ---------------- FUSED agg+GEMM: out = [mean_r(h) | h] @ Wc + b ----------------
// A is gathered on the fly: per slab (32 dims), each A row is the mean over that
// row's (node, rel) CSR segment. Reg-staged double buffer overlaps gather w/ mma.
template <int BN, int DIM>
__global__ void __launch_bounds__(512) k_gemm_f(
        const __half* __restrict__ hs, __half* __restrict__ outh,
        float* __restrict__ outf,
        const __half* __restrict__ Wc,   // packed transposed [BN][Ktot]
        const float* __restrict__ bias, int M) {
    const int Ktot = DIM * 5;
    const int SPR = DIM / 32;        // slabs per relation
    const int NSLAB_R = 4 * SPR;
    const int NSLAB = 5 * SPR;
    const int NT = BN / 32;

    extern __shared__ __half sm[];
    __half* As = sm;                 // 2*128*40
    __half* Bs = sm + 2 * 128 * 40;  // 2*BN*40
#define FAS(b, m, k) As[((b) * 128 + (m)) * 40 + (k)]
#define FBS(b, n, k) Bs[((b) * BN + (n)) * 40 + (k)]

    int tid = threadIdx.x;
    int lane = tid & 31, warp = tid >> 5;
    int lr = lane >> 2, lc = lane & 3;
    int wm = (warp & 3) * 32;
    int wn = (warp >> 2) * (BN / 4);
    int row0 = blockIdx.x * 128;

    // gather mapping: 4 threads per A row, each owns 8 halves (16B) of the slab
    int grow = tid >> 2, quad = tid & 3;
    int gnode = min(row0 + grow, M - 1);
    int begr[4], cr[4];
    float invr[4];
#pragma unroll
    for (int r = 0; r < 4; r++) {
        begr[r] = g_off[gnode * 4 + r];
        cr[r] = g_cnt[gnode * 4 + r];
        invr[r] = 1.0f / fmaxf((float)cr[r], 1.0f);
    }

    float acc[2][BN / 32][4];
#pragma unroll
    for (int i = 0; i < 2; i++)
#pragma unroll
        for (int j = 0; j < NT; j++)
#pragma unroll
            for (int q = 0; q < 4; q++) acc[i][j][q] = 0.f;

    float ga[8];
    uint4 gself;
    bool gselfp = false;

    auto gatherA = [&](int s) {
        if (s < NSLAB_R) {
            gselfp = false;
            int rel = s / SPR;
            int off = (s - rel * SPR) * 32;
#pragma unroll
            for (int i = 0; i < 8; i++) ga[i] = 0.f;
            int beg = begr[rel], c = cr[rel];
            const __half* base = hs + off + quad * 8;
            int si = (c > 0) ? g_eidx[beg] : 0;
            for (int k = 0; k < c; k++) {
                int sn = (k + 1 < c) ? g_eidx[beg + k + 1] : 0;
                uint4 u = *(const uint4*)(base + (size_t)si * DIM);
                float2 f0 = __half22float2(*(__half2*)&u.x);
                float2 f1 = __half22float2(*(__half2*)&u.y);
                float2 f2 = __half22float2(*(__half2*)&u.z);
                float2 f3 = __half22float2(*(__half2*)&u.w);
                ga[0] += f0.x; ga[1] += f0.y; ga[2] += f1.x; ga[3] += f1.y;
                ga[4] += f2.x; ga[5] += f2.y; ga[6] += f3.x; ga[7] += f3.y;
                si = sn;
            }
            float inv = invr[rel];
#pragma unroll
            for (int i = 0; i < 8; i++) ga[i] *= inv;
        } else {
            gselfp = true;
            int off = (s - NSLAB_R) * 32;
            gself = *(const uint4*)(hs + (size_t)gnode * DIM + off + quad * 8);
        }
    };
    auto storeA = [&](int buf) {
        __half* p = &FAS(buf, grow, quad * 8);
        if (gselfp) {
            *(uint4*)p = gself;
        } else {
            uint4 u;
            u.x = h2u(__floats2half2_rn(ga[0], ga[1]));
            u.y = h2u(__floats2half2_rn(ga[2], ga[3]));
            u.z = h2u(__floats2half2_rn(ga[4], ga[5]));
            u.w = h2u(__floats2half2_rn(ga[6], ga[7]));
            *(uint4*)p = u;
        }
    };
    auto stageB = [&](int s, int buf) {
        if (BN == 256) {
            int bn = tid >> 1, bo = (tid & 1) * 16;
            const __half* bp = Wc + (size_t)bn * Ktot + s * 32;
            cp16h(&FBS(buf, bn, bo), bp + bo, true);
            cp16h(&FBS(buf, bn, bo + 8), bp + bo + 8, true);
        } else {
            int bn = tid >> 2, bo = (tid & 3) * 8;
            cp16h(&FBS(buf, bn, bo), Wc + (size_t)bn * Ktot + s * 32 + bo, true);
        }
    };

    stageB(0, 0); CP_COMMIT();
    gatherA(0);
    storeA(0);
    CP_WAIT0();
    __syncthreads();

    for (int s = 0; s < NSLAB; s++) {
        int buf = s & 1;
        if (s + 1 < NSLAB) {
            stageB(s + 1, buf ^ 1);
            CP_COMMIT();
            gatherA(s + 1);
        }
#pragma unroll
        for (int ks = 0; ks < 2; ks++) {
            int kb = ks * 16 + 2 * lc;
            unsigned af[2][4];
#pragma unroll
            for (int mt = 0; mt < 2; mt++) {
                int r = wm + mt * 16 + lr;
                af[mt][0] = *(unsigned*)&FAS(buf, r, kb);
                af[mt][1] = *(unsigned*)&FAS(buf, r + 8, kb);
                af[mt][2] = *(unsigned*)&FAS(buf, r, kb + 8);
                af[mt][3] = *(unsigned*)&FAS(buf, r + 8, kb + 8);
            }
#pragma unroll
            for (int nt = 0; nt < NT; nt++) {
                int n = wn + nt * 8 + lr;
                unsigned b0 = *(unsigned*)&FBS(buf, n, kb);
                unsigned b1 = *(unsigned*)&FBS(buf, n, kb + 8);
#pragma unroll
                for (int mt = 0; mt < 2; mt++) mma_f16(acc[mt][nt], af[mt], b0, b1);
            }
        }
        if (s + 1 < NSLAB) {
            storeA(buf ^ 1);
            CP_WAIT0();
        }
        __syncthreads();
    }

#pragma unroll
    for (int mt = 0; mt < 2; mt++) {
        int r = row0 + wm + mt * 16 + lr;
#pragma unroll
        for (int nt = 0; nt < NT; nt++) {
            int c = wn + nt * 8 + 2 * lc;
            float bx = bias[c], by = bias[c + 1];
            if (BN == 256) {   // layers 1-2: relu, fp16 out
                float v0x = fmaxf(acc[mt][nt][0] + bx, 0.f);
                float v0y = fmaxf(acc[mt][nt][1] + by, 0.f);
                float v1x = fmaxf(acc[mt][nt][2] + bx, 0.f);
                float v1y = fmaxf(acc[mt][nt][3] + by, 0.f);
                if (r < M)     *(__half2*)(outh + (size_t)r * BN + c) = __floats2half2_rn(v0x, v0y);
                if (r + 8 < M) *(__half2*)(outh + (size_t)(r + 8) * BN + c) = __floats2half2_rn(v1x, v1y);
            } else {           // layer 3: fp32 out, no relu
                if (r < M) *(float2*)(outf + (size_t)r * BN + c) =
                    make_float2(acc[mt][nt][0] + bx, acc[mt][nt][1] + by);
                if (r + 8 < M) *(float2*)(outf + (size_t)(r + 8) * BN + c) =
                    make_float2(acc[mt][nt][2] + bx, acc[mt][nt][3] + by);
            }
        }
    }
#undef FAS
#undef FBS
}

// ---------------- graph pooling ----------------
__global__ void k_gcount(const int* __restrict__ gid, int N) {
    int n = blockIdx.x * blockDim.x + threadIdx.x;
    unsigned act = __ballot_sync(0xffffffffu, n < N);
    if (n < N) {
        int g = gid[n];
        unsigned m = __match_any_sync(act, g);
        if ((threadIdx.x & 31) == __ffs(m) - 1) atomicAdd(&g_gcnt[g], (float)__popc(m));
    }
}
__global__ void k_pool(const int* __restrict__ gid, int N) {
    int j = threadIdx.x;
    int n0 = blockIdx.x * 64;
    if (n0 >= N) return;
    int nend = min(n0 + 64, N);
    int curg = gid[n0];
    float acc = 0.f;
    for (int n = n0; n < nend; n++) {
        int g = gid[n];
        if (g != curg) {
            atomicAdd(&g_pool[curg * 128 + j], acc);
            acc = 0.f;
            curg = g;
        }
        acc += g_h3[(size_t)n * 128 + j];
    }
    atomicAdd(&g_pool[curg * 128 + j], acc);
}

// ---------------- finalize ----------------
__global__ void k_final(const float* __restrict__ wfc, const float* __restrict__ bfc,
                        float* __restrict__ out, int out_size) {
    __shared__ float emb[16 * 128];
    __shared__ float part[4];
    __shared__ float sc[16];
    int j = threadIdx.x;
    for (int b = 0; b < 16; b++) {
        float c = fmaxf(g_gcnt[b], 1.0f);
        float v = g_pool[b * 128 + j] / c;
        v = (v >= 0.f) ? v : 0.01f * v;
        emb[b * 128 + j] = v;
    }
    float w = wfc[j];
    for (int b = 0; b < 16; b++) {
        float p = emb[b * 128 + j] * w;
        for (int off = 16; off; off >>= 1) p += __shfl_down_sync(0xffffffffu, p, off);
        if ((j & 31) == 0) part[j >> 5] = p;
        __syncthreads();
        if (j == 0) {
            float s = part[0] + part[1] + part[2] + part[3] + bfc[0];
            sc[b] = 1.0f / (1.0f + expf(-s));
        }
        __syncthreads();
    }
    if (out_size >= 2064) {
        if (j < 16) out[j] = sc[j];
        int base = out_size - 2048;
        for (int b = 0; b < 16; b++) out[base + b * 128 + j] = emb[b * 128 + j];
    } else if (out_size >= 2048) {
        for (int b = 0; b < 16; b++) out[b * 128 + j] = emb[b * 128 + j];
    } else {
        if (j < 16 && j < out_size) out[j] = sc[j];
    }
}

// ---------------- launch ----------------
extern "C" void kernel_launch(void* const* d_in, const int* in_sizes, int n_in,
                              void* d_out, int out_size) {
    const float* x   = (const float*)d_in[0];
    const float* Wnt = (const float*)d_in[1];
    const float* Wr1 = (const float*)d_in[2];
    const float* Ws1 = (const float*)d_in[3];
    const float* b1  = (const float*)d_in[4];
    const float* Wr2 = (const float*)d_in[5];
    const float* Ws2 = (const float*)d_in[6];
    const float* b2  = (const float*)d_in[7];
    const float* Wr3 = (const float*)d_in[8];
    const float* Ws3 = (const float*)d_in[9];
    const float* b3  = (const float*)d_in[10];
    const float* wfc = (const float*)d_in[11];
    const float* bfc = (const float*)d_in[12];
    const int* esrc  = (const int*)d_in[13];
    const int* edst  = (const int*)d_in[14];
    const int* etyp  = (const int*)d_in[15];
    const int* ntyp  = (const int*)d_in[16];
    const int* gid   = (const int*)d_in[17];
    int N = in_sizes[16];
    int E = in_sizes[13];
    int NR = N * 4;
    int NB = (NR + 1023) / 1024;

    const int SMEM_ENC  = (3 * 128 * 40 + 3 * 128 * 40) * 2;   // 61440
    const int SMEM_F256 = (2 * 128 * 40 + 2 * 256 * 40) * 2;   // 61440
    const int SMEM_F128 = (2 * 128 * 40 + 2 * 128 * 40) * 2;   // 40960
    cudaFuncSetAttribute(k_enc_h, cudaFuncAttributeMaxDynamicSharedMemorySize, SMEM_ENC);
    cudaFuncSetAttribute(k_gemm_f<256, 128>, cudaFuncAttributeMaxDynamicSharedMemorySize, SMEM_F256);
    cudaFuncSetAttribute(k_gemm_f<256, 256>, cudaFuncAttributeMaxDynamicSharedMemorySize, SMEM_F256);
    cudaFuncSetAttribute(k_gemm_f<128, 256>, cudaFuncAttributeMaxDynamicSharedMemorySize, SMEM_F128);

    __half *wb_dev, *xh_dev, *h0_dev, *h1_dev, *h2_dev;
    float* h3_dev;
    cudaGetSymbolAddress((void**)&wb_dev, g_wbh);
    cudaGetSymbolAddress((void**)&xh_dev, g_xh);
    cudaGetSymbolAddress((void**)&h0_dev, g_h0h);
    cudaGetSymbolAddress((void**)&h1_dev, g_h1h);
    cudaGetSymbolAddress((void**)&h2_dev, g_h2h);
    cudaGetSymbolAddress((void**)&h3_dev, g_h3);
    const int W1_OFF = 0, W2_OFF = 163840, W3_OFF = 491520;

    int initN = (NIDX_CAP > NR) ? NIDX_CAP : NR;
    k_init<<<(initN + 255) / 256, 256>>>(NR);
    k_cvt_x<<<(N * 16 + 255) / 256, 256>>>((const float4*)x, (uint4*)xh_dev, N * 16);
    k_pack_wnt<<<(7 * 16384 + 255) / 256, 256>>>(Wnt);
    k_pack_wb<<<(640 * 256 + 255) / 256, 256>>>(Wr1, Ws1, wb_dev + W1_OFF, 512, 640, 256, 640 * 256);
    k_pack_wb<<<(1280 * 256 + 255) / 256, 256>>>(Wr2, Ws2, wb_dev + W2_OFF, 1024, 1280, 256, 1280 * 256);
    k_pack_wb<<<(1280 * 128 + 255) / 256, 256>>>(Wr3, Ws3, wb_dev + W3_OFF, 1024, 1280, 128, 1280 * 128);

    // edge CSR build
    k_hist<<<(E + 255) / 256, 256>>>(edst, etyp, E);
    k_scan1<<<NB, 1024>>>(NR);
    k_scan2<<<1, 1024>>>(NB);
    k_scan3<<<NB, 1024>>>(NR);
    k_bucket<<<(E + 255) / 256, 256>>>(esrc, edst, etyp, E);

    // node-type sort + encoder
    k_hist_nt<<<(N + 255) / 256, 256>>>(ntyp, N);
    k_nt_offsets<<<1, 32>>>();
    k_bucket_nt<<<(N + 255) / 256, 256>>>(ntyp, N);
    int gx_enc = (N + 7 * 128 + 127) / 128;
    k_enc_h<<<gx_enc, 256, SMEM_ENC>>>();

    int gx = (N + 127) / 128;

    // fused agg+GEMM layers
    k_gemm_f<256, 128><<<gx, 512, SMEM_F256>>>(h0_dev, h1_dev, nullptr, wb_dev + W1_OFF, b1, N);
    k_gemm_f<256, 256><<<gx, 512, SMEM_F256>>>(h1_dev, h2_dev, nullptr, wb_dev + W2_OFF, b2, N);
    k_gemm_f<128, 256><<<gx, 512, SMEM_F128>>>(h2_dev, nullptr, h3_dev, wb_dev + W3_OFF, b3, N);

    // pooling + head
    k_gcount<<<(N + 255) / 256, 256>>>(gid, N);
    k_pool<<<(N + 63) / 64, 128>>>(gid, N);
    k_zero_out<<<(out_size + 255) / 256, 256>>>((float*)d_out, out_size);
    k_final<<<1, 128>>>(wfc, bfc, (float*)d_out, out_size);
}

// round 10
// speedup vs baseline: 1.5330x; 1.5330x over previous
#include <cuda_runtime.h>
#include <cuda_fp16.h>
#include <math.h>

#define NN 100000
#define EE 1000000
#define NRMAX (NN * 4)
#define NIDX_CAP 100992

// ---------------- device scratch ----------------
__device__ __half g_h0h[(size_t)NN * 128];
__device__ __half g_h1h[(size_t)NN * 256];
__device__ __half g_h2h[(size_t)NN * 256];
__device__ float  g_h3[(size_t)NN * 128];
__device__ __half g_aggh[(size_t)NN * 4 * 256];
__device__ __half g_xh[(size_t)NN * 128];
__device__ __half g_wnth[7 * 128 * 128];   // transposed [t][n][k]
__device__ __half g_wbh[655360];           // packed transposed [n][Ktot] per layer
__device__ float g_pool[16 * 128];
__device__ float g_gcnt[16];

__device__ int g_cnt[NRMAX];
__device__ int g_off[NRMAX];
__device__ int g_cur[NRMAX];
__device__ int g_bsum[1024];
__device__ int g_eidx[EE];
__device__ int g_nt_cnt[8];
__device__ int g_nt_off[8];
__device__ int g_nt_cur[8];
__device__ int g_nidx[NIDX_CAP];

// ---------------- helpers ----------------
__device__ __forceinline__ void cp16h(__half* dst, const __half* src, bool pred) {
    unsigned d = (unsigned)__cvta_generic_to_shared(dst);
    int sz = pred ? 16 : 0;
    asm volatile("cp.async.ca.shared.global [%0], [%1], 16, %2;\n"
                 :: "r"(d), "l"(src), "r"(sz));
}
#define CP_COMMIT() asm volatile("cp.async.commit_group;\n")
#define CP_WAIT1()  asm volatile("cp.async.wait_group 1;\n")
#define CP_WAIT0()  asm volatile("cp.async.wait_group 0;\n")

__device__ __forceinline__ void mma_f16(float* c, const unsigned* a, unsigned b0, unsigned b1) {
    asm volatile(
        "mma.sync.aligned.m16n8k16.row.col.f32.f16.f16.f32 "
        "{%0,%1,%2,%3},{%4,%5,%6,%7},{%8,%9},{%0,%1,%2,%3};"
        : "+f"(c[0]), "+f"(c[1]), "+f"(c[2]), "+f"(c[3])
        : "r"(a[0]), "r"(a[1]), "r"(a[2]), "r"(a[3]), "r"(b0), "r"(b1));
}
__device__ __forceinline__ void ldsm_x4(unsigned& r0, unsigned& r1, unsigned& r2,
                                        unsigned& r3, unsigned addr) {
    asm volatile("ldmatrix.sync.aligned.m8n8.x4.shared.b16 {%0,%1,%2,%3}, [%4];"
                 : "=r"(r0), "=r"(r1), "=r"(r2), "=r"(r3) : "r"(addr));
}
__device__ __forceinline__ unsigned h2u(__half2 h) { return *(unsigned*)&h; }

// ---------------- init / conversion kernels ----------------
__global__ void k_init(int NR) {
    int i = blockIdx.x * blockDim.x + threadIdx.x;
    if (i < NR) g_cnt[i] = 0;
    if (i < NIDX_CAP) g_nidx[i] = -1;
    if (i < 8) g_nt_cnt[i] = 0;
    if (i < 2048) g_pool[i] = 0.f;
    if (i < 16) g_gcnt[i] = 0.f;
}
__global__ void k_zero_out(float* out, int n) {
    int i = blockIdx.x * blockDim.x + threadIdx.x;
    if (i < n) out[i] = 0.f;
}
__global__ void k_cvt_x(const float4* __restrict__ src, uint4* __restrict__ dst, int n8) {
    int i = blockIdx.x * blockDim.x + threadIdx.x;
    if (i < n8) {
        float4 a = src[i * 2], b = src[i * 2 + 1];
        uint4 o;
        o.x = h2u(__floats2half2_rn(a.x, a.y));
        o.y = h2u(__floats2half2_rn(a.z, a.w));
        o.z = h2u(__floats2half2_rn(b.x, b.y));
        o.w = h2u(__floats2half2_rn(b.z, b.w));
        dst[i] = o;
    }
}
__global__ void k_pack_wnt(const float* __restrict__ src) {
    int i = blockIdx.x * blockDim.x + threadIdx.x;
    if (i < 7 * 128 * 128) {
        int t = i >> 14, rem = i & 16383;
        int n = rem >> 7, k = rem & 127;
        g_wnth[i] = __float2half_rn(src[(t << 14) + (k << 7) + n]);
    }
}
__global__ void k_pack_wb(const float* __restrict__ Wr, const float* __restrict__ Ws,
                          __half* __restrict__ dst, int K1, int Ktot, int Nout, int total) {
    int j = blockIdx.x * blockDim.x + threadIdx.x;
    if (j < total) {
        int n = j / Ktot, kk = j - n * Ktot;
        float v = (kk < K1) ? Wr[(size_t)kk * Nout + n]
                            : Ws[(size_t)(kk - K1) * Nout + n];
        dst[j] = __float2half_rn(v);
    }
}

// ---------------- edge CSR build ----------------
__global__ void k_hist(const int* __restrict__ dst, const int* __restrict__ typ, int E) {
    int e = blockIdx.x * blockDim.x + threadIdx.x;
    if (e < E) atomicAdd(&g_cnt[dst[e] * 4 + typ[e]], 1);
}
__device__ __forceinline__ int block_scan_incl(int v, int* ws) {
    int lane = threadIdx.x & 31, wid = threadIdx.x >> 5;
#pragma unroll
    for (int o = 1; o < 32; o <<= 1) {
        int t = __shfl_up_sync(0xffffffffu, v, o);
        if (lane >= o) v += t;
    }
    if (lane == 31) ws[wid] = v;
    __syncthreads();
    if (wid == 0) {
        int w = (lane < (int)(blockDim.x >> 5)) ? ws[lane] : 0;
#pragma unroll
        for (int o = 1; o < 32; o <<= 1) {
            int t = __shfl_up_sync(0xffffffffu, w, o);
            if (lane >= o) w += t;
        }
        ws[lane] = w;
    }
    __syncthreads();
    return v + (wid > 0 ? ws[wid - 1] : 0);
}
__global__ void k_scan1(int n) {
    __shared__ int ws[32];
    int i = blockIdx.x * 1024 + threadIdx.x;
    int c = (i < n) ? g_cnt[i] : 0;
    int incl = block_scan_incl(c, ws);
    if (i < n) g_off[i] = incl - c;
    if (threadIdx.x == 1023) g_bsum[blockIdx.x] = incl;
}
__global__ void k_scan2(int nb) {
    __shared__ int ws[32];
    int i = threadIdx.x;
    int v = (i < nb) ? g_bsum[i] : 0;
    int incl = block_scan_incl(v, ws);
    if (i < nb) g_bsum[i] = incl - v;
}
__global__ void k_scan3(int n) {
    int i = blockIdx.x * 1024 + threadIdx.x;
    if (i < n) {
        int o = g_off[i] + g_bsum[i >> 10];
        g_off[i] = o;
        g_cur[i] = o;
    }
}
__global__ void k_bucket(const int* __restrict__ src, const int* __restrict__ dst,
                         const int* __restrict__ typ, int E) {
    int e = blockIdx.x * blockDim.x + threadIdx.x;
    if (e < E) {
        int key = dst[e] * 4 + typ[e];
        int pos = atomicAdd(&g_cur[key], 1);
        g_eidx[pos] = src[e];
    }
}

// ---------------- node-type counting sort ----------------
__global__ void k_hist_nt(const int* __restrict__ nt, int N) {
    int n = blockIdx.x * blockDim.x + threadIdx.x;
    unsigned act = __ballot_sync(0xffffffffu, n < N);
    if (n < N) {
        int t = nt[n];
        unsigned m = __match_any_sync(act, t);
        if ((threadIdx.x & 31) == __ffs(m) - 1) atomicAdd(&g_nt_cnt[t], __popc(m));
    }
}
__global__ void k_nt_offsets() {
    if (threadIdx.x == 0) {
        int off = 0;
        for (int t = 0; t < 7; t++) {
            g_nt_off[t] = off;
            g_nt_cur[t] = off;
            off += ((g_nt_cnt[t] + 127) / 128) * 128;
        }
        g_nt_off[7] = off;
    }
}
__global__ void k_bucket_nt(const int* __restrict__ nt, int N) {
    int n = blockIdx.x * blockDim.x + threadIdx.x;
    unsigned act = __ballot_sync(0xffffffffu, n < N);
    if (n < N) {
        int t = nt[n];
        unsigned m = __match_any_sync(act, t);
        int leader = __ffs(m) - 1;
        unsigned lt = (1u << (threadIdx.x & 31)) - 1u;
        int rank = __popc(m & lt);
        int base = 0;
        if ((threadIdx.x & 31) == leader) base = atomicAdd(&g_nt_cur[t], __popc(m));
        base = __shfl_sync(act, base, leader);
        g_nidx[base + rank] = n;
    }
}

// ---------------- encoder: fp16 tc GEMM with row indirection ----------------
__global__ void __launch_bounds__(256) k_enc_h() {
    extern __shared__ __half sm[];
    __half* As = sm;                 // 3*128*40
    __half* Bs = sm + 3 * 128 * 40;  // 3*128*40
#define HAS(b, m, k) As[((b) * 128 + (m)) * 40 + (k)]
#define HBS(b, n, k) Bs[((b) * 128 + (n)) * 40 + (k)]

    int base = blockIdx.x * 128;
    if (base >= g_nt_off[7]) return;
    int t = 0;
    while (t < 6 && base >= g_nt_off[t + 1]) t++;
    const __half* W = g_wnth + (size_t)t * 16384;

    int tid = threadIdx.x;
    int lane = tid & 31, warp = tid >> 5;
    int lr = lane >> 2, lc = lane & 3;
    int wm = (warp & 3) * 32;
    int wn = (warp >> 2) * 64;

    int ar = tid >> 1;
    int ao = (tid & 1) * 16;
    int anode = g_nidx[base + ar];
    const __half* asrc = g_xh + (size_t)max(anode, 0) * 128;
    bool avalid = anode >= 0;

    float acc[2][8][4];
#pragma unroll
    for (int i = 0; i < 2; i++)
#pragma unroll
        for (int j = 0; j < 8; j++)
#pragma unroll
            for (int q = 0; q < 4; q++) acc[i][j][q] = 0.f;

    auto stage = [&](int s, int buf) {
        int k0 = s * 32;
        cp16h(&HAS(buf, ar, ao), asrc + k0 + ao, avalid);
        cp16h(&HAS(buf, ar, ao + 8), asrc + k0 + ao + 8, avalid);
        const __half* bp = W + (size_t)ar * 128 + k0;
        cp16h(&HBS(buf, ar, ao), bp + ao, true);
        cp16h(&HBS(buf, ar, ao + 8), bp + ao + 8, true);
    };

    const int NSLAB = 4;
    stage(0, 0); CP_COMMIT();
    stage(1, 1); CP_COMMIT();
    for (int s = 0; s < NSLAB; s++) {
        if (s + 1 < NSLAB) CP_WAIT1(); else CP_WAIT0();
        __syncthreads();
        if (s + 2 < NSLAB) { stage(s + 2, (s + 2) % 3); CP_COMMIT(); }
        int buf = s % 3;
#pragma unroll
        for (int ks = 0; ks < 2; ks++) {
            int kb = ks * 16 + 2 * lc;
            unsigned af[2][4];
#pragma unroll
            for (int mt = 0; mt < 2; mt++) {
                int r = wm + mt * 16 + lr;
                af[mt][0] = *(unsigned*)&HAS(buf, r, kb);
                af[mt][1] = *(unsigned*)&HAS(buf, r + 8, kb);
                af[mt][2] = *(unsigned*)&HAS(buf, r, kb + 8);
                af[mt][3] = *(unsigned*)&HAS(buf, r + 8, kb + 8);
            }
#pragma unroll
            for (int nt = 0; nt < 8; nt++) {
                int n = wn + nt * 8 + lr;
                unsigned b0 = *(unsigned*)&HBS(buf, n, kb);
                unsigned b1 = *(unsigned*)&HBS(buf, n, kb + 8);
#pragma unroll
                for (int mt = 0; mt < 2; mt++) mma_f16(acc[mt][nt], af[mt], b0, b1);
            }
        }
        __syncthreads();
    }

#pragma unroll
    for (int mt = 0; mt < 2; mt++) {
        int r0 = base + wm + mt * 16 + lr;
        int n0 = g_nidx[r0], n1 = g_nidx[r0 + 8];
#pragma unroll
        for (int nt = 0; nt < 8; nt++) {
            int c = wn + nt * 8 + 2 * lc;
            if (n0 >= 0) *(__half2*)(g_h0h + (size_t)n0 * 128 + c) =
                __floats2half2_rn(acc[mt][nt][0], acc[mt][nt][1]);
            if (n1 >= 0) *(__half2*)(g_h0h + (size_t)n1 * 128 + c) =
                __floats2half2_rn(acc[mt][nt][2], acc[mt][nt][3]);
        }
    }
#undef HAS
#undef HBS
}

// ---------------- aggregation: one warp per (node,rel), fp16 gather ----------------
template <int DIM>
__global__ void k_aggh(int layer, int NR4) {
    const __half* __restrict__ h = (layer == 1) ? g_h0h : (layer == 2) ? g_h1h : g_h2h;
    int w = (blockIdx.x * blockDim.x + threadIdx.x) >> 5;
    if (w >= NR4) return;
    int lane = threadIdx.x & 31;
    const int V = DIM / 32;  // 8 or 4 halves per lane
    int beg = g_off[w], c = g_cnt[w];
    float a[8];
#pragma unroll
    for (int i = 0; i < 8; i++) a[i] = 0.f;
    int s = (c > 0) ? g_eidx[beg] : 0;
    for (int k = 0; k < c; k++) {
        int sn = (k + 1 < c) ? g_eidx[beg + k + 1] : 0;
        const __half* row = h + (size_t)s * DIM + lane * V;
        if (V == 8) {
            uint4 u = *(const uint4*)row;
            float2 f0 = __half22float2(*(__half2*)&u.x);
            float2 f1 = __half22float2(*(__half2*)&u.y);
            float2 f2 = __half22float2(*(__half2*)&u.z);
            float2 f3 = __half22float2(*(__half2*)&u.w);
            a[0] += f0.x; a[1] += f0.y; a[2] += f1.x; a[3] += f1.y;
            a[4] += f2.x; a[5] += f2.y; a[6] += f3.x; a[7] += f3.y;
        } else {
            uint2 u = *(const uint2*)row;
            float2 f0 = __half22float2(*(__half2*)&u.x);
            float2 f1 = __half22float2(*(__half2*)&u.y);
            a[0] += f0.x; a[1] += f0.y; a[2] += f1.x; a[3] += f1.y;
        }
        s = sn;
    }
    float inv = 1.0f / fmaxf((float)c, 1.0f);
    __half* o = g_aggh + (size_t)w * DIM + lane * V;
    if (V == 8) {
        uint4 u;
        u.x = h2u(__floats2half2_rn(a[0] * inv, a[1] * inv));
        u.y = h2u(__floats2half2_rn(a[2] * inv, a[3] * inv));
        u.z = h2u(__floats2half2_rn(a[4] * inv, a[5] * inv));
        u.w = h2u(__floats2half2_rn(a[6] * inv, a[7] * inv));
        *(uint4*)o = u;
    } else {
        uint2 u;
        u.x = h2u(__floats2half2_rn(a[0] * inv, a[1] * inv));
        u.y = h2u(__floats2half2_rn(a[2] * inv, a[3] * inv));
        *(uint2*)o = u;
    }
}

// ---------------- main GEMM (fp16, ldmatrix frags): out = [mean | h] @ Wc + b ----------------
template <int BN>
__global__ void __launch_bounds__(512) k_gemm_h(
        const __half* __restrict__ Wc,   // packed transposed [BN][Ktot]
        const float* __restrict__ bias, int layer, int M, int DIM) {
    const __half* __restrict__ hs = (layer == 1) ? g_h0h : (layer == 2) ? g_h1h : g_h2h;
    __half* __restrict__ outh = (layer == 1) ? g_h1h : g_h2h;
    const int K1 = DIM * 4;
    const int Ktot = DIM * 5;
    const int NSLAB = Ktot / 32;
    const int NT = BN / 32;
    const int NTP = NT / 2;

    extern __shared__ __half sm[];
    __half* As = sm;                     // 3*128*40
    __half* Bs = sm + 3 * 128 * 40;      // 3*BN*40
#define HAS(b, m, k) As[((b) * 128 + (m)) * 40 + (k)]
#define HBS(b, n, k) Bs[((b) * BN + (n)) * 40 + (k)]

    int tid = threadIdx.x;
    int lane = tid & 31, warp = tid >> 5;
    int lr = lane >> 2, lc = lane & 3;
    int wm = (warp & 3) * 32;
    int wn = (warp >> 2) * (BN / 4);
    int row0 = blockIdx.x * 128;

    int ar = tid >> 2, achk = (tid & 3) * 8;
    int arow = row0 + ar;
    bool avalid = arow < M;
    int crow = avalid ? arow : (M - 1);
    const __half* aggp = g_aggh + (size_t)crow * K1;
    const __half* hsp = hs + (size_t)crow * DIM;

    // ldmatrix source addresses (lane-mapped)
    int g = lane >> 3, sub = lane & 7;
    unsigned as_base = (unsigned)__cvta_generic_to_shared(As);
    unsigned bs_base = (unsigned)__cvta_generic_to_shared(Bs);
    const unsigned ABUF = 128 * 40 * 2;
    const unsigned BBUF = BN * 40 * 2;
    unsigned addrA[2], addrB[NTP];
#pragma unroll
    for (int mt = 0; mt < 2; mt++)
        addrA[mt] = as_base + (((wm + mt * 16 + (g & 1) * 8 + sub) * 40) + (g >> 1) * 8) * 2;
#pragma unroll
    for (int p = 0; p < NTP; p++)
        addrB[p] = bs_base + (((wn + p * 16 + (g >> 1) * 8 + sub) * 40) + (g & 1) * 8) * 2;

    float acc[2][BN / 32][4];
#pragma unroll
    for (int i = 0; i < 2; i++)
#pragma unroll
        for (int j = 0; j < NT; j++)
#pragma unroll
            for (int q = 0; q < 4; q++) acc[i][j][q] = 0.f;

    auto stage = [&](int s, int buf) {
        int col = s * 32 + achk;
        const __half* ap = (col < K1) ? (aggp + col) : (hsp + col - K1);
        cp16h(&HAS(buf, ar, achk), ap, avalid);
        if (BN == 256) {
            int bn = tid >> 1, bo = (tid & 1) * 16;
            const __half* bp = Wc + (size_t)bn * Ktot + s * 32;
            cp16h(&HBS(buf, bn, bo), bp + bo, true);
            cp16h(&HBS(buf, bn, bo + 8), bp + bo + 8, true);
        } else {
            int bn = tid >> 2, bo = (tid & 3) * 8;
            const __half* bp = Wc + (size_t)bn * Ktot + s * 32;
            cp16h(&HBS(buf, bn, bo), bp + bo, true);
        }
    };

    stage(0, 0); CP_COMMIT();
    stage(1, 1); CP_COMMIT();
    for (int s = 0; s < NSLAB; s++) {
        if (s + 1 < NSLAB) CP_WAIT1(); else CP_WAIT0();
        __syncthreads();
        if (s + 2 < NSLAB) { stage(s + 2, (s + 2) % 3); CP_COMMIT(); }
        int buf = s % 3;
        unsigned aoff = buf * ABUF, boff = buf * BBUF;
#pragma unroll
        for (int ks = 0; ks < 2; ks++) {
            unsigned koff = ks * 32;
            unsigned af[2][4];
#pragma unroll
            for (int mt = 0; mt < 2; mt++)
                ldsm_x4(af[mt][0], af[mt][1], af[mt][2], af[mt][3],
                        addrA[mt] + aoff + koff);
#pragma unroll
            for (int p = 0; p < NTP; p++) {
                unsigned b00, b01, b10, b11;
                ldsm_x4(b00, b01, b10, b11, addrB[p] + boff + koff);
#pragma unroll
                for (int mt = 0; mt < 2; mt++) {
                    mma_f16(acc[mt][2 * p],     af[mt], b00, b01);
                    mma_f16(acc[mt][2 * p + 1], af[mt], b10, b11);
                }
            }
        }
        __syncthreads();
    }

#pragma unroll
    for (int mt = 0; mt < 2; mt++) {
        int r = row0 + wm + mt * 16 + lr;
#pragma unroll
        for (int nt = 0; nt < NT; nt++) {
            int c = wn + nt * 8 + 2 * lc;
            float bx = bias[c], by = bias[c + 1];
            if (BN == 256) {   // layers 1-2: relu, fp16 out
                float v0x = fmaxf(acc[mt][nt][0] + bx, 0.f);
                float v0y = fmaxf(acc[mt][nt][1] + by, 0.f);
                float v1x = fmaxf(acc[mt][nt][2] + bx, 0.f);
                float v1y = fmaxf(acc[mt][nt][3] + by, 0.f);
                if (r < M)     *(__half2*)(outh + (size_t)r * BN + c) = __floats2half2_rn(v0x, v0y);
                if (r + 8 < M) *(__half2*)(outh + (size_t)(r + 8) * BN + c) = __floats2half2_rn(v1x, v1y);
            } else {           // layer 3: fp32 out, no relu
                if (r < M) *(float2*)(g_h3 + (size_t)r * BN + c) =
                    make_float2(acc[mt][nt][0] + bx, acc[mt][nt][1] + by);
                if (r + 8 < M) *(float2*)(g_h3 + (size_t)(r + 8) * BN + c) =
                    make_float2(acc[mt][nt][2] + bx, acc[mt][nt][3] + by);
            }
        }
    }
#undef HAS
#undef HBS
}

// ---------------- graph pooling ----------------
__global__ void k_gcount(const int* __restrict__ gid, int N) {
    int n = blockIdx.x * blockDim.x + threadIdx.x;
    unsigned act = __ballot_sync(0xffffffffu, n < N);
    if (n < N) {
        int g = gid[n];
        unsigned m = __match_any_sync(act, g);
        if ((threadIdx.x & 31) == __ffs(m) - 1) atomicAdd(&g_gcnt[g], (float)__popc(m));
    }
}
__global__ void k_pool(const int* __restrict__ gid, int N) {
    int j = threadIdx.x;
    int n0 = blockIdx.x * 64;
    if (n0 >= N) return;
    int nend = min(n0 + 64, N);
    int curg = gid[n0];
    float acc = 0.f;
    for (int n = n0; n < nend; n++) {
        int g = gid[n];
        if (g != curg) {
            atomicAdd(&g_pool[curg * 128 + j], acc);
            acc = 0.f;
            curg = g;
        }
        acc += g_h3[(size_t)n * 128 + j];
    }
    atomicAdd(&g_pool[curg * 128 + j], acc);
}

// ---------------- finalize ----------------
__global__ void k_final(const float* __restrict__ wfc, const float* __restrict__ bfc,
                        float* __restrict__ out, int out_size) {
    __shared__ float emb[16 * 128];
    __shared__ float part[4];
    __shared__ float sc[16];
    int j = threadIdx.x;
    for (int b = 0; b < 16; b++) {
        float c = fmaxf(g_gcnt[b], 1.0f);
        float v = g_pool[b * 128 + j] / c;
        v = (v >= 0.f) ? v : 0.01f * v;
        emb[b * 128 + j] = v;
    }
    float w = wfc[j];
    for (int b = 0; b < 16; b++) {
        float p = emb[b * 128 + j] * w;
        for (int off = 16; off; off >>= 1) p += __shfl_down_sync(0xffffffffu, p, off);
        if ((j & 31) == 0) part[j >> 5] = p;
        __syncthreads();
        if (j == 0) {
            float s = part[0] + part[1] + part[2] + part[3] + bfc[0];
            sc[b] = 1.0f / (1.0f + expf(-s));
        }
        __syncthreads();
    }
    if (out_size >= 2064) {
        if (j < 16) out[j] = sc[j];
        int base = out_size - 2048;
        for (int b = 0; b < 16; b++) out[base + b * 128 + j] = emb[b * 128 + j];
    } else if (out_size >= 2048) {
        for (int b = 0; b < 16; b++) out[b * 128 + j] = emb[b * 128 + j];
    } else {
        if (j < 16 && j < out_size) out[j] = sc[j];
    }
}

// ---------------- launch ----------------
extern "C" void kernel_launch(void* const* d_in, const int* in_sizes, int n_in,
                              void* d_out, int out_size) {
    const float* x   = (const float*)d_in[0];
    const float* Wnt = (const float*)d_in[1];
    const float* Wr1 = (const float*)d_in[2];
    const float* Ws1 = (const float*)d_in[3];
    const float* b1  = (const float*)d_in[4];
    const float* Wr2 = (const float*)d_in[5];
    const float* Ws2 = (const float*)d_in[6];
    const float* b2  = (const float*)d_in[7];
    const float* Wr3 = (const float*)d_in[8];
    const float* Ws3 = (const float*)d_in[9];
    const float* b3  = (const float*)d_in[10];
    const float* wfc = (const float*)d_in[11];
    const float* bfc = (const float*)d_in[12];
    const int* esrc  = (const int*)d_in[13];
    const int* edst  = (const int*)d_in[14];
    const int* etyp  = (const int*)d_in[15];
    const int* ntyp  = (const int*)d_in[16];
    const int* gid   = (const int*)d_in[17];
    int N = in_sizes[16];
    int E = in_sizes[13];
    int NR = N * 4;
    int NB = (NR + 1023) / 1024;

    const int SMEM_ENC  = (3 * 128 * 40 + 3 * 128 * 40) * 2;   // 61440
    const int SMEM_G256 = (3 * 128 * 40 + 3 * 256 * 40) * 2;   // 92160
    const int SMEM_G128 = (3 * 128 * 40 + 3 * 128 * 40) * 2;   // 61440
    cudaFuncSetAttribute(k_enc_h, cudaFuncAttributeMaxDynamicSharedMemorySize, SMEM_ENC);
    cudaFuncSetAttribute(k_gemm_h<256>, cudaFuncAttributeMaxDynamicSharedMemorySize, SMEM_G256);
    cudaFuncSetAttribute(k_gemm_h<128>, cudaFuncAttributeMaxDynamicSharedMemorySize, SMEM_G128);

    __half *wb_dev, *xh_dev;
    cudaGetSymbolAddress((void**)&wb_dev, g_wbh);
    cudaGetSymbolAddress((void**)&xh_dev, g_xh);
    const int W1_OFF = 0, W2_OFF = 163840, W3_OFF = 491520;

    int initN = (NIDX_CAP > NR) ? NIDX_CAP : NR;
    k_init<<<(initN + 255) / 256, 256>>>(NR);
    k_cvt_x<<<(N * 16 + 255) / 256, 256>>>((const float4*)x, (uint4*)xh_dev, N * 16);
    k_pack_wnt<<<(7 * 16384 + 255) / 256, 256>>>(Wnt);
    k_pack_wb<<<(640 * 256 + 255) / 256, 256>>>(Wr1, Ws1, wb_dev + W1_OFF, 512, 640, 256, 640 * 256);
    k_pack_wb<<<(1280 * 256 + 255) / 256, 256>>>(Wr2, Ws2, wb_dev + W2_OFF, 1024, 1280, 256, 1280 * 256);
    k_pack_wb<<<(1280 * 128 + 255) / 256, 256>>>(Wr3, Ws3, wb_dev + W3_OFF, 1024, 1280, 128, 1280 * 128);

    // edge CSR build
    k_hist<<<(E + 255) / 256, 256>>>(edst, etyp, E);
    k_scan1<<<NB, 1024>>>(NR);
    k_scan2<<<1, 1024>>>(NB);
    k_scan3<<<NB, 1024>>>(NR);
    k_bucket<<<(E + 255) / 256, 256>>>(esrc, edst, etyp, E);

    // node-type sort + encoder
    k_hist_nt<<<(N + 255) / 256, 256>>>(ntyp, N);
    k_nt_offsets<<<1, 32>>>();
    k_bucket_nt<<<(N + 255) / 256, 256>>>(ntyp, N);
    int gx_enc = (N + 7 * 128 + 127) / 128;
    k_enc_h<<<gx_enc, 256, SMEM_ENC>>>();

    int gagg = (NR * 32 + 255) / 256;
    int gx = (N + 127) / 128;

    // layer 1 (128 -> 256, relu)
    k_aggh<128><<<gagg, 256>>>(1, NR);
    k_gemm_h<256><<<gx, 512, SMEM_G256>>>(wb_dev + W1_OFF, b1, 1, N, 128);

    // layer 2 (256 -> 256, relu)
    k_aggh<256><<<gagg, 256>>>(2, NR);
    k_gemm_h<256><<<gx, 512, SMEM_G256>>>(wb_dev + W2_OFF, b2, 2, N, 256);

    // layer 3 (256 -> 128, no relu)
    k_aggh<256><<<gagg, 256>>>(3, NR);
    k_gemm_h<128><<<gx, 512, SMEM_G128>>>(wb_dev + W3_OFF, b3, 3, N, 256);

    // pooling + head
    k_gcount<<<(N + 255) / 256, 256>>>(gid, N);
    k_pool<<<(N + 63) / 64, 128>>>(gid, N);
    k_zero_out<<<(out_size + 255) / 256, 256>>>((float*)d_out, out_size);
    k_final<<<1, 128>>>(wfc, bfc, (float*)d_out, out_size);
}